// round 3
// baseline (speedup 1.0000x reference)
#include <cuda_runtime.h>
#include <cuda_bf16.h>

// Constant-memory staging for the two small matrices.
// E: extrinsic 4x4 row-major (16 floats). K: intrinsic 3x4 row-major (12 floats).
__constant__ float c_E[16];
__constant__ float c_K[12];

__global__ __launch_bounds__(256)
void gaussian_project_kernel(const float* __restrict__ points,     // [N,3]
                             const float4* __restrict__ quats,     // [N,4]
                             const float* __restrict__ scales,     // [N,3]
                             float* __restrict__ out,              // [7N]
                             int N) {
    int i = blockIdx.x * blockDim.x + threadIdx.x;
    if (i >= N) return;

    // ---- loads ----
    const float px = points[3 * i + 0];
    const float py = points[3 * i + 1];
    const float pz = points[3 * i + 2];
    const float4 q = quats[i];
    const float sx = scales[3 * i + 0];
    const float sy = scales[3 * i + 1];
    const float sz = scales[3 * i + 2];

    // ---- camera transform: cam = E @ [p;1] ----
    const float camx = fmaf(c_E[0], px, fmaf(c_E[1], py, fmaf(c_E[2], pz, c_E[3])));
    const float camy = fmaf(c_E[4], px, fmaf(c_E[5], py, fmaf(c_E[6], pz, c_E[7])));
    const float camz = fmaf(c_E[8], px, fmaf(c_E[9], py, fmaf(c_E[10], pz, c_E[11])));
    const float camw = fmaf(c_E[12], px, fmaf(c_E[13], py, fmaf(c_E[14], pz, c_E[15])));

    const float invw = __frcp_rn(camw);
    const float c3x = camx * invw;
    const float c3y = camy * invw;
    const float c3z = camz * invw;

    // ---- projection: proj = K @ [cam3;1]; pp = proj[:2]/proj[2] ----
    const float fx = c_K[0], cx = c_K[2];
    const float fy = c_K[5], cy = c_K[6];
    const float projx = fmaf(fx, c3x, fmaf(c_K[1], c3y, fmaf(cx, c3z, c_K[3])));
    const float projy = fmaf(c_K[4], c3x, fmaf(fy, c3y, fmaf(cy, c3z, c_K[7])));
    const float projz = fmaf(c_K[8], c3x, fmaf(c_K[9], c3y, fmaf(c_K[10], c3z, c_K[11])));
    const float invpz = __frcp_rn(projz);
    const float ppx = projx * invpz;
    const float ppy = projy * invpz;

    // ---- quaternion -> rotation ----
    const float qn = rsqrtf(fmaf(q.x, q.x, fmaf(q.y, q.y, fmaf(q.z, q.z, q.w * q.w))));
    const float w = q.x * qn, x = q.y * qn, y = q.z * qn, z = q.w * qn;

    const float r00 = 1.0f - 2.0f * (y * y + z * z);
    const float r01 = 2.0f * (x * y - w * z);
    const float r02 = 2.0f * (x * z + w * y);
    const float r10 = 2.0f * (x * y + w * z);
    const float r11 = 1.0f - 2.0f * (x * x + z * z);
    const float r12 = 2.0f * (y * z - w * x);
    const float r20 = 2.0f * (x * z - w * y);
    const float r21 = 2.0f * (y * z + w * x);
    const float r22 = 1.0f - 2.0f * (x * x + y * y);

    // ---- M = R * diag(s); cov3d = M M^T (symmetric) ----
    const float m00 = r00 * sx, m01 = r01 * sy, m02 = r02 * sz;
    const float m10 = r10 * sx, m11 = r11 * sy, m12 = r12 * sz;
    const float m20 = r20 * sx, m21 = r21 * sy, m22 = r22 * sz;

    const float s00 = fmaf(m00, m00, fmaf(m01, m01, m02 * m02));
    const float s01 = fmaf(m00, m10, fmaf(m01, m11, m02 * m12));
    const float s02 = fmaf(m00, m20, fmaf(m01, m21, m02 * m22));
    const float s11 = fmaf(m10, m10, fmaf(m11, m11, m12 * m12));
    const float s12 = fmaf(m10, m20, fmaf(m11, m21, m12 * m22));
    const float s22 = fmaf(m20, m20, fmaf(m21, m21, m22 * m22));

    // ---- Jacobian rows combined with R_ext: T2 = J[:2] @ E[:3,:3] ----
    const float invz = __frcp_rn(c3z);
    const float invz2 = invz * invz;
    const float a = fx * invz;
    const float b = fy * invz;
    const float cterm = -fx * c3x * invz2;
    const float dterm = -fy * c3y * invz2;

    const float t00 = fmaf(a, c_E[0], cterm * c_E[8]);
    const float t01 = fmaf(a, c_E[1], cterm * c_E[9]);
    const float t02 = fmaf(a, c_E[2], cterm * c_E[10]);
    const float t10 = fmaf(b, c_E[4], dterm * c_E[8]);
    const float t11 = fmaf(b, c_E[5], dterm * c_E[9]);
    const float t12 = fmaf(b, c_E[6], dterm * c_E[10]);

    // ---- cov2d = T2 @ cov3d @ T2^T ----
    const float u0x = fmaf(s00, t00, fmaf(s01, t01, s02 * t02));
    const float u0y = fmaf(s01, t00, fmaf(s11, t01, s12 * t02));
    const float u0z = fmaf(s02, t00, fmaf(s12, t01, s22 * t02));
    const float u1x = fmaf(s00, t10, fmaf(s01, t11, s02 * t12));
    const float u1y = fmaf(s01, t10, fmaf(s11, t11, s12 * t12));
    const float u1z = fmaf(s02, t10, fmaf(s12, t11, s22 * t12));

    const float c00 = fmaf(t00, u0x, fmaf(t01, u0y, t02 * u0z));
    const float c01 = fmaf(t00, u1x, fmaf(t01, u1y, t02 * u1z));
    const float c10 = fmaf(t10, u0x, fmaf(t11, u0y, t12 * u0z));
    const float c11 = fmaf(t10, u1x, fmaf(t11, u1y, t12 * u1z));

    // ---- stores: [2N pp][N z][4N cov] ----
    reinterpret_cast<float2*>(out)[i] = make_float2(ppx, ppy);
    out[2 * N + i] = camz;
    reinterpret_cast<float4*>(out + 3 * (size_t)N)[i] = make_float4(c00, c01, c10, c11);
}

extern "C" void kernel_launch(void* const* d_in, const int* in_sizes, int n_in,
                              void* d_out, int out_size) {
    const float* points = (const float*)d_in[0];
    const float4* quats = (const float4*)d_in[1];
    const float* scales = (const float*)d_in[2];
    const float* extr = (const float*)d_in[3];   // 16 floats
    const float* intr = (const float*)d_in[4];   // 12 floats

    const int N = in_sizes[0] / 3;

    // Stage the small matrices into constant memory (device-to-device async
    // memcpy -> valid graph memcpy nodes).
    cudaMemcpyToSymbolAsync(c_E, extr, 16 * sizeof(float), 0,
                            cudaMemcpyDeviceToDevice, 0);
    cudaMemcpyToSymbolAsync(c_K, intr, 12 * sizeof(float), 0,
                            cudaMemcpyDeviceToDevice, 0);

    const int threads = 256;
    const int blocks = (N + threads - 1) / threads;
    gaussian_project_kernel<<<blocks, threads>>>(points, quats, scales,
                                                 (float*)d_out, N);
}